// round 13
// baseline (speedup 1.0000x reference)
#include <cuda_runtime.h>
#include <math.h>
#include <stdint.h>

// ---------------------------------------------------------------------------
// Problem constants (fixed by setup_inputs)
// ---------------------------------------------------------------------------
#define Bn 64
#define Ln 512
#define Hn 256
#define H3 768
#define An 128
#define NDEPTH 4
#define NROWS (Ln * Bn)          /* 32768, t-major: row = t*Bn + b */
#define XPW 896                  /* 768 (gru proj) + 128 (action proj) */
#define OUT_ACT 16384            /* Bn*Hn */
#define OUT_POL 147456           /* OUT_ACT + Bn*NDEPTH*Ln */

#define CSIZE 8                  /* cluster size */
#define SLOTS 112                /* U columns per CTA (96 gru + 16 action) */
#define GRUS 96

// Static smem layout for scan (float offsets)
#define SM_BAR  0                /* 2 mbarriers (u64): pb_bar @0, h_bar @8 bytes */
#define SM_HS   4                /* h: [row][k] 4*256 = 1024 */
#define SM_PART 1028             /* split-k partials: 448 float4 = 1792 */
#define SM_ZB   2820             /* z: 112 slots * 5 (pad) = 560 */
#define SM_AP   3380             /* tanh action acts: 16 * 4 = 64 */
#define SM_PB   3444             /* 8 ranks * 4 rows * 4 = 128 */
#define SM_AW0  3572             /* 16 */
#define SM_AW1  3588             /* 16 */
#define SM_AB1  3604             /* 16 */
#define SM_BA2  3620             /* 2 */
#define SM_TOT  3624             /* 14496 bytes */

// ---------------------------------------------------------------------------
// Static scratch
// ---------------------------------------------------------------------------
__device__ float g_hseq[NROWS * Hn];                 // 32 MB
__device__ float g_xpz[(size_t)NROWS * XPW];         // 112 MB
__device__ float g_wpack[256 * XPW];                 // [W | W_action_1]
__device__ float g_upack[256 * XPW];                 // [rank][slot][k] layout
__device__ unsigned char g_maskA[NROWS];
__device__ unsigned char g_maskB[NROWS];

// ---------------------------------------------------------------------------
// PTX helpers (cluster / DSMEM / mbarrier)
// ---------------------------------------------------------------------------
__device__ __forceinline__ uint32_t smem_u32(const void* p) {
    uint32_t a;
    asm("{ .reg .u64 t; cvta.to.shared.u64 t, %1; cvt.u32.u64 %0, t; }"
        : "=r"(a) : "l"(p));
    return a;
}
__device__ __forceinline__ uint32_t mapa_c(uint32_t a, uint32_t r) {
    uint32_t d;
    asm("mapa.shared::cluster.u32 %0, %1, %2;" : "=r"(d) : "r"(a), "r"(r));
    return d;
}
__device__ __forceinline__ void stc(uint32_t a, float v) {
    asm volatile("st.shared::cluster.f32 [%0], %1;" :: "r"(a), "f"(v) : "memory");
}
__device__ __forceinline__ void stc64(uint32_t a, unsigned long long v) {
    asm volatile("st.shared::cluster.b64 [%0], %1;" :: "r"(a), "l"(v) : "memory");
}
__device__ __forceinline__ void cluster_sync() {
    asm volatile("barrier.cluster.arrive.aligned;" ::: "memory");
    asm volatile("barrier.cluster.wait.aligned;" ::: "memory");
}
__device__ __forceinline__ uint32_t ctarank() {
    uint32_t r; asm("mov.u32 %0, %%cluster_ctarank;" : "=r"(r)); return r;
}
__device__ __forceinline__ void mbar_init(uint32_t a, uint32_t cnt) {
    asm volatile("mbarrier.init.shared.b64 [%0], %1;" :: "r"(a), "r"(cnt) : "memory");
}
__device__ __forceinline__ void cfence() {
    asm volatile("fence.acq_rel.cluster;" ::: "memory");
}
__device__ __forceinline__ void arrive_remote(uint32_t bar, uint32_t r) {
    asm volatile(
        "{\n\t"
        ".reg .b32 ra;\n\t"
        "mapa.shared::cluster.u32 ra, %0, %1;\n\t"
        "mbarrier.arrive.shared::cluster.b64 _, [ra];\n\t"
        "}"
        :: "r"(bar), "r"(r) : "memory");
}
__device__ __forceinline__ void mbwait(uint32_t bar, uint32_t parity) {
    uint32_t done;
    asm volatile(
        "{\n\t"
        ".reg .pred p;\n\t"
        "mbarrier.try_wait.parity.acquire.cta.shared::cta.b64 p, [%1], %2;\n\t"
        "selp.b32 %0, 1, 0, p;\n\t"
        "}"
        : "=r"(done) : "r"(bar), "r"(parity) : "memory");
    if (!done) {
        asm volatile(
            "{\n\t"
            ".reg .pred P1;\n\t"
            "WAIT_LOOP_%=:\n\t"
            "mbarrier.try_wait.parity.acquire.cta.shared::cta.b64 P1, [%0], %1, 0x989680;\n\t"
            "@P1 bra.uni WAIT_DONE_%=;\n\t"
            "bra.uni WAIT_LOOP_%=;\n\t"
            "WAIT_DONE_%=:\n\t"
            "}"
            :: "r"(bar), "r"(parity) : "memory");
    }
}

// ---------------------------------------------------------------------------
// Pack weights.
// which=0: g_wpack = [W | Wa1] plain [k][896].
// which=1: g_upack[((rank*112 + slot)*256) + k] = U/Ua1[k][c]
// ---------------------------------------------------------------------------
__global__ void pack_k(const float* __restrict__ Wm,
                       const float* __restrict__ Wa, int which)
{
    int i = blockIdx.x * blockDim.x + threadIdx.x;
    if (i >= 256 * XPW) return;
    int k = i / XPW, c = i % XPW;
    float v = (c < H3) ? Wm[k * H3 + c] : Wa[k * An + (c - H3)];
    if (which == 0) {
        g_wpack[i] = v;
    } else {
        int rank, s;
        if (c < H3) { rank = c & 7; s = c >> 3; }
        else        { int a = c - H3; rank = a & 7; s = GRUS + (a >> 3); }
        g_upack[(rank * SLOTS + s) * 256 + k] = v;
    }
}

__global__ void initmask_k(const int* __restrict__ m)
{
    int i = blockIdx.x * blockDim.x + threadIdx.x;
    if (i < NROWS) {
        int t = i >> 6, b = i & 63;
        g_maskA[i] = (m[b * Ln + t] != 0) ? 1 : 0;
    }
}

// ---------------------------------------------------------------------------
// GEMM: C[32768 x N] = A[32768 x 256] @ B[256 x N] (+ bias)   (unchanged)
// ---------------------------------------------------------------------------
__global__ void __launch_bounds__(256) gemm_k(
    const float* __restrict__ Aex, const float* __restrict__ Bex,
    const float* __restrict__ bias, int N, int mode)
{
    const float* __restrict__ A = mode ? g_hseq : Aex;
    const float* __restrict__ B = mode ? g_wpack : Bex;
    float* __restrict__ C       = mode ? g_xpz  : g_hseq;
    const int permute = (mode == 0);

    __shared__ __align__(16) float As[16][132];
    __shared__ __align__(16) float Bs[16][128];

    const int tid = threadIdx.x;
    const int bx = blockIdx.x, by = blockIdx.y;
    const int tx = tid & 15, ty = tid >> 4;

    float acc[8][8];
#pragma unroll
    for (int i = 0; i < 8; i++)
#pragma unroll
        for (int j = 0; j < 8; j++) acc[i][j] = 0.0f;

    const int ar  = tid & 127;
    const int akh = (tid >> 7) * 8;
    const int brow = tid >> 4;
    const int bcol = (tid & 15) * 8;

    for (int kt = 0; kt < 256; kt += 16) {
        int m = by * 128 + ar;
        long arow = permute ? ((long)(m & 63) * Ln + (m >> 6)) : (long)m;
        const float* ap = A + arow * 256 + kt + akh;
        float4 a0 = *(const float4*)ap;
        float4 a1 = *(const float4*)(ap + 4);
        As[akh + 0][ar] = a0.x; As[akh + 1][ar] = a0.y;
        As[akh + 2][ar] = a0.z; As[akh + 3][ar] = a0.w;
        As[akh + 4][ar] = a1.x; As[akh + 5][ar] = a1.y;
        As[akh + 6][ar] = a1.z; As[akh + 7][ar] = a1.w;

        const float* bp = B + (long)(kt + brow) * N + bx * 128 + bcol;
        *(float4*)&Bs[brow][bcol]     = *(const float4*)bp;
        *(float4*)&Bs[brow][bcol + 4] = *(const float4*)(bp + 4);
        __syncthreads();

#pragma unroll
        for (int kk = 0; kk < 16; kk++) {
            float a8[8], b8[8];
            *(float4*)&a8[0] = *(const float4*)&As[kk][ty * 8];
            *(float4*)&a8[4] = *(const float4*)&As[kk][ty * 8 + 4];
            *(float4*)&b8[0] = *(const float4*)&Bs[kk][tx * 8];
            *(float4*)&b8[4] = *(const float4*)&Bs[kk][tx * 8 + 4];
#pragma unroll
            for (int i = 0; i < 8; i++)
#pragma unroll
                for (int j = 0; j < 8; j++)
                    acc[i][j] = fmaf(a8[i], b8[j], acc[i][j]);
        }
        __syncthreads();
    }

    float bv[8];
#pragma unroll
    for (int j = 0; j < 8; j++)
        bv[j] = bias ? bias[bx * 128 + tx * 8 + j] : 0.0f;

#pragma unroll
    for (int i = 0; i < 8; i++) {
        long row = by * 128 + ty * 8 + i;
        float* cp = C + row * N + bx * 128 + tx * 8;
        float4 o0, o1;
        o0.x = acc[i][0] + bv[0]; o0.y = acc[i][1] + bv[1];
        o0.z = acc[i][2] + bv[2]; o0.w = acc[i][3] + bv[3];
        o1.x = acc[i][4] + bv[4]; o1.y = acc[i][5] + bv[5];
        o1.z = acc[i][6] + bv[6]; o1.w = acc[i][7] + bv[7];
        *(float4*)cp       = o0;
        *(float4*)(cp + 4) = o1;
    }
}

// ---------------------------------------------------------------------------
// Row LayerNorm of g_xpz[:, 0:768] in place (gamma0/beta0). 1 block/row.
// ---------------------------------------------------------------------------
__global__ void __launch_bounds__(256) lnx_k(const float* __restrict__ gam,
                                             const float* __restrict__ bet)
{
    long row = blockIdx.x;
    float* p = g_xpz + row * XPW;
    int tid = threadIdx.x;
    float v0 = p[tid], v1 = p[tid + 256], v2 = p[tid + 512];
    float s = v0 + v1 + v2;
    float q = v0 * v0 + v1 * v1 + v2 * v2;

    __shared__ float rs[8], rq[8], st[2];
#pragma unroll
    for (int off = 16; off; off >>= 1) {
        s += __shfl_down_sync(0xffffffffu, s, off);
        q += __shfl_down_sync(0xffffffffu, q, off);
    }
    if ((tid & 31) == 0) { rs[tid >> 5] = s; rq[tid >> 5] = q; }
    __syncthreads();
    if (tid == 0) {
        float S = 0.f, Q = 0.f;
#pragma unroll
        for (int i = 0; i < 8; i++) { S += rs[i]; Q += rq[i]; }
        float mean = S * (1.0f / 768.0f);
        float var  = Q * (1.0f / 768.0f) - mean * mean;
        st[0] = mean;
        st[1] = rsqrtf(var + 1e-5f);
    }
    __syncthreads();
    float mean = st[0], r = st[1];
    p[tid]       = (v0 - mean) * r * gam[tid]       + bet[tid];
    p[tid + 256] = (v1 - mean) * r * gam[tid + 256] + bet[tid + 256];
    p[tid + 512] = (v2 - mean) * r * gam[tid + 512] + bet[tid + 512];
}

// ---------------------------------------------------------------------------
// Cluster scan v3: 16 clusters x 8 CTAs x 512 threads.
// Roles: tid<448 GEMV (U in regs) + split-k reduce; tid>=448 (warps 14-15)
// LN/gates (2 cols x 1 row each). Cross-CTA sync via 2 DSMEM mbarriers
// (pb_bar: LN/logit partials ready; h_bar: h(t) broadcast complete), one
// elected arrive-fanout per CTA per phase. No barrier.cluster in the loop.
// ---------------------------------------------------------------------------
__global__ void __launch_bounds__(512, 1) __cluster_dims__(CSIZE, 1, 1)
scan_k(const float* __restrict__ bias3, const float* __restrict__ ba1,
       const float* __restrict__ wa2,   const float* __restrict__ ba2,
       const float* __restrict__ gam1,  const float* __restrict__ bet1,
       float* __restrict__ out, int out_size, int dep, int ping)
{
    __shared__ __align__(16) float sm[SM_TOT];
    float* hsf  = sm + SM_HS;
    float* part = sm + SM_PART;
    float* zb   = sm + SM_ZB;
    float* ap   = sm + SM_AP;
    float* pb   = sm + SM_PB;
    float* aw0  = sm + SM_AW0;
    float* aw1  = sm + SM_AW1;
    float* ab1  = sm + SM_AB1;
    float* b2s  = sm + SM_BA2;

    const int tid = threadIdx.x;
    const uint32_t rank = ctarank();
    const int bbase = (blockIdx.x / CSIZE) * 4;
    const uint32_t sm32 = smem_u32(sm);
    const uint32_t pb_bar = sm32;          // u64 @ byte 0
    const uint32_t h_bar  = sm32 + 8;      // u64 @ byte 8

    const unsigned char* __restrict__ min_ = ping ? g_maskB : g_maskA;
    unsigned char* __restrict__       mout = ping ? g_maskA : g_maskB;

    if (tid == 0) { mbar_init(pb_bar, CSIZE); mbar_init(h_bar, CSIZE); }

    // ---- GEMV identity + U registers (tid < 448 only) ----
    const int gs = tid % SLOTS;
    const int gq = tid / SLOTS;
    float4 uq[16];
    if (tid < 448) {
        const float4* up = (const float4*)(g_upack + ((rank * SLOTS + gs) * 256 + gq * 64));
#pragma unroll
        for (int i = 0; i < 16; i++) uq[i] = up[i];
    }

    // ---- gate identity (tid >= 448): 2 cols x 1 row ----
    const int gt = tid - 448;
    const int grow = gt >> 4, gq16 = gt & 15;
    const int myc0 = 16 * gq16 + (int)rank;
    const int myc1 = myc0 + 8;
    const int myrow = bbase + grow;
    float cg00=0,cg01=0,cg02=0, cg10=0,cg11=0,cg12=0;
    float ce00=0,ce01=0,ce02=0, ce10=0,ce11=0,ce12=0;
    float cb00=0,cb01=0,cb02=0, cb10=0,cb11=0,cb12=0;
    if (tid >= 448) {
        cg00 = gam1[myc0]; cg01 = gam1[myc0+256]; cg02 = gam1[myc0+512];
        cg10 = gam1[myc1]; cg11 = gam1[myc1+256]; cg12 = gam1[myc1+512];
        ce00 = bet1[myc0]; ce01 = bet1[myc0+256]; ce02 = bet1[myc0+512];
        ce10 = bet1[myc1]; ce11 = bet1[myc1+256]; ce12 = bet1[myc1+512];
        cb00 = bias3[myc0]; cb01 = bias3[myc0+256]; cb02 = bias3[myc0+512];
        cb10 = bias3[myc1]; cb11 = bias3[myc1+256]; cb12 = bias3[myc1+512];
    }
    if (tid < 16) {
        int a = 8 * tid + (int)rank;
        aw0[tid] = wa2[a * 2]; aw1[tid] = wa2[a * 2 + 1]; ab1[tid] = ba1[a];
    }
    if (tid < 2) b2s[tid] = ba2[tid];
    // h0 = 0
    hsf[tid] = 0.0f; hsf[tid + 512] = 0.0f;
    float hprev0 = 0.0f, hprev1 = 0.0f;
    __syncthreads();
    cluster_sync();   // publish mbarrier inits + zero h across cluster

    for (int t = 0; t < Ln; t++) {
        // -------- prefetches (issued before any wait) --------
        float xp00=0,xp01=0,xp02=0, xp10=0,xp11=0,xp12=0; int mt = 0;
        if (tid >= 448) {
            long base = (long)(t * Bn + myrow) * XPW;
            xp00 = g_xpz[base + myc0];
            xp01 = g_xpz[base + myc0 + 256];
            xp02 = g_xpz[base + myc0 + 512];
            xp10 = g_xpz[base + myc1];
            xp11 = g_xpz[base + myc1 + 256];
            xp12 = g_xpz[base + myc1 + 512];
            mt   = min_[t * Bn + myrow];
        }
        float xav = 0.f;
        if (tid >= 384 && tid < 448) {       // reduce-stage action threads
            int s2 = tid >> 2, r2 = tid & 3;
            int a = 8 * (s2 - GRUS) + (int)rank;
            xav = g_xpz[(long)(t * Bn + bbase + r2) * XPW + H3 + a];
        }

        // -------- GEMV (tid < 448): wait h(t-1), quarter-dot 4 rows --------
        if (tid < 448) {
            if (t) mbwait(h_bar, (uint32_t)((t - 1) & 1));
            float a0 = 0.f, a1 = 0.f, a2 = 0.f, a3 = 0.f;
            const float4* h0 = (const float4*)(hsf + gq * 64);
            const float4* h1 = (const float4*)(hsf + 256 + gq * 64);
            const float4* h2 = (const float4*)(hsf + 512 + gq * 64);
            const float4* h3 = (const float4*)(hsf + 768 + gq * 64);
#pragma unroll
            for (int i = 0; i < 16; i++) {
                float4 u4 = uq[i];
                float4 v0 = h0[i], v1 = h1[i], v2 = h2[i], v3 = h3[i];
                a0 = fmaf(u4.x, v0.x, a0); a0 = fmaf(u4.y, v0.y, a0);
                a0 = fmaf(u4.z, v0.z, a0); a0 = fmaf(u4.w, v0.w, a0);
                a1 = fmaf(u4.x, v1.x, a1); a1 = fmaf(u4.y, v1.y, a1);
                a1 = fmaf(u4.z, v1.z, a1); a1 = fmaf(u4.w, v1.w, a1);
                a2 = fmaf(u4.x, v2.x, a2); a2 = fmaf(u4.y, v2.y, a2);
                a2 = fmaf(u4.z, v2.z, a2); a2 = fmaf(u4.w, v2.w, a2);
                a3 = fmaf(u4.x, v3.x, a3); a3 = fmaf(u4.y, v3.y, a3);
                a3 = fmaf(u4.z, v3.z, a3); a3 = fmaf(u4.w, v3.w, a3);
            }
            ((float4*)part)[gq * SLOTS + gs] = make_float4(a0, a1, a2, a3);
        }
        __syncthreads();

        // -------- split-k reduce (tid < 448): z[slot][row] --------
        if (tid < 448) {
            int s2 = tid >> 2, r2 = tid & 3;
            const float* pp = part + s2 * 4 + r2;
            float z = pp[0] + pp[448] + pp[896] + pp[1344];
            if (s2 < GRUS) zb[s2 * 5 + r2] = z;
            else {
                int qa = s2 - GRUS;
                ap[qa * 4 + r2] = tanhf(xav + z + ab1[qa]);
            }
        }
        __syncthreads();

        // -------- gate warps (tid >= 448): LN partials, logits, gates -----
        if (tid >= 448) {
            int j0 = 2 * gq16, j1 = j0 + 1;
            float z00 = zb[j0*5 + grow], z01 = zb[(j0+32)*5 + grow], z02 = zb[(j0+64)*5 + grow];
            float z10 = zb[j1*5 + grow], z11 = zb[(j1+32)*5 + grow], z12 = zb[(j1+64)*5 + grow];
            float sv = z00 + z01 + z02 + z10 + z11 + z12;
            float qv = z00*z00 + z01*z01 + z02*z02 + z10*z10 + z11*z11 + z12*z12;
#pragma unroll
            for (int o = 1; o < 16; o <<= 1) {
                sv += __shfl_xor_sync(0xffffffffu, sv, o);
                qv += __shfl_xor_sync(0xffffffffu, qv, o);
            }
            float l0 = 0.f, l1 = 0.f;
            if (gq16 == 0) {
#pragma unroll
                for (int qi = 0; qi < 16; qi++) {
                    float ta = ap[qi * 4 + grow];
                    l0 = fmaf(ta, aw0[qi], l0);
                    l1 = fmaf(ta, aw1[qi], l1);
                }
            }
            int srcl = tid & 16;
            l0 = __shfl_sync(0xffffffffu, l0, srcl);
            l1 = __shfl_sync(0xffffffffu, l1, srcl);
            if (gq16 < 8) {
                unsigned long long sq, ll;
                asm("mov.b64 %0, {%1,%2};" : "=l"(sq) : "f"(sv), "f"(qv));
                asm("mov.b64 %0, {%1,%2};" : "=l"(ll) : "f"(l0), "f"(l1));
                uint32_t loc = sm32 + (uint32_t)(SM_PB + (rank * 4 + grow) * 4) * 4u;
                uint32_t pa = mapa_c(loc, (uint32_t)gq16);
                stc64(pa, sq); stc64(pa + 8, ll);
            }
            asm volatile("bar.sync 1, 64;" ::: "memory");
            if (gt == 0) {
                cfence();
#pragma unroll
                for (uint32_t ii = 0; ii < CSIZE; ii++) arrive_remote(pb_bar, ii);
            }
            mbwait(pb_bar, (uint32_t)(t & 1));

            // ---- gates: global stats, 2 columns ----
            float S = 0.f, Q = 0.f, L0 = 0.f, L1 = 0.f;
#pragma unroll
            for (int ii = 0; ii < CSIZE; ii++) {
                float4 v = *(const float4*)&pb[(ii * 4 + grow) * 4];
                S += v.x; Q += v.y; L0 += v.z; L1 += v.w;
            }
            float mean = S * (1.0f / 768.0f);
            float var  = Q * (1.0f / 768.0f) - mean * mean;
            float rstd = rsqrtf(var + 1e-5f);

            float hp0 = (z00 - mean) * rstd * cg00 + ce00;
            float hp1 = (z01 - mean) * rstd * cg01 + ce01;
            float hp2 = (z02 - mean) * rstd * cg02 + ce02;
            float rg = 1.0f / (1.0f + expf(-(xp00 + hp0 + cb00)));
            float zg = 1.0f / (1.0f + expf(-(xp01 + hp1 + cb01)));
            float hh = tanhf(xp02 + rg * hp2 + cb02);
            float hn = zg * hprev0 + (1.0f - zg) * hh;
            float ho0 = mt ? hn : hprev0;
            hprev0 = ho0;

            hp0 = (z10 - mean) * rstd * cg10 + ce10;
            hp1 = (z11 - mean) * rstd * cg11 + ce11;
            hp2 = (z12 - mean) * rstd * cg12 + ce12;
            rg = 1.0f / (1.0f + expf(-(xp10 + hp0 + cb10)));
            zg = 1.0f / (1.0f + expf(-(xp11 + hp1 + cb11)));
            hh = tanhf(xp12 + rg * hp2 + cb12);
            hn = zg * hprev1 + (1.0f - zg) * hh;
            float ho1 = mt ? hn : hprev1;
            hprev1 = ho1;

            long gb = (long)(t * Bn + myrow) * Hn;
            g_hseq[gb + myc0] = ho0;
            g_hseq[gb + myc1] = ho1;
            uint32_t loc0 = sm32 + (uint32_t)(SM_HS + grow * 256 + myc0) * 4u;
            uint32_t loc1 = sm32 + (uint32_t)(SM_HS + grow * 256 + myc1) * 4u;
#pragma unroll
            for (uint32_t ii = 0; ii < CSIZE; ii++) {
                stc(mapa_c(loc0, ii), ho0);
                stc(mapa_c(loc1, ii), ho1);
            }
            if (gq16 == 0) {
                float ls0 = b2s[0] + L0, ls1 = b2s[1] + L1;
                int act = (ls1 > ls0) && mt;   // pol1>pol0 <=> l1>l0
                if (rank == 0) {
                    float mx = fmaxf(ls0, ls1);
                    float e0 = expf(ls0 - mx), e1 = expf(ls1 - mx);
                    float inv = 1.0f / (e0 + e1);
                    int b = myrow;
                    int ai = OUT_ACT + (b * NDEPTH + dep) * Ln + t;
                    if (ai < out_size) out[ai] = (float)act;
                    int pi = OUT_POL + ((b * NDEPTH + dep) * Ln + t) * 2;
                    if (pi + 1 < out_size) { out[pi] = e0 * inv; out[pi + 1] = e1 * inv; }
                    mout[t * Bn + b] = (unsigned char)act;
                }
            }
            asm volatile("bar.sync 1, 64;" ::: "memory");
            if (gt == 0) {
                cfence();
#pragma unroll
                for (uint32_t ii = 0; ii < CSIZE; ii++) arrive_remote(h_bar, ii);
            }
        }
    }
    cluster_sync();   // no CTA exits while remote stores/arrives may be in flight
}

// ---------------------------------------------------------------------------
// output = h_seq[-1] (t = 511), (B, H)
// ---------------------------------------------------------------------------
__global__ void copyout_k(float* __restrict__ out, int out_size)
{
    int i = blockIdx.x * blockDim.x + threadIdx.x;
    if (i < Bn * Hn && i < out_size)
        out[i] = g_hseq[(long)(511 * Bn + (i >> 8)) * Hn + (i & 255)];
}

// ---------------------------------------------------------------------------
// launch
// ---------------------------------------------------------------------------
extern "C" void kernel_launch(void* const* d_in, const int* in_sizes, int n_in,
                              void* d_out, int out_size)
{
    const float* x      = (const float*)d_in[0];
    const int*   maskp  = (const int*)  d_in[1];
    const float* W_emb  = (const float*)d_in[2];
    const float* b_emb  = (const float*)d_in[3];
    const float* W      = (const float*)d_in[4];
    const float* U      = (const float*)d_in[5];
    const float* b      = (const float*)d_in[6];
    const float* Wa1    = (const float*)d_in[7];
    const float* Ua1    = (const float*)d_in[8];
    const float* ba1    = (const float*)d_in[9];
    const float* Wa2    = (const float*)d_in[10];
    const float* ba2    = (const float*)d_in[11];
    const float* gammas = (const float*)d_in[12];
    const float* betas  = (const float*)d_in[13];
    float* out = (float*)d_out;

    pack_k<<<(256 * XPW + 255) / 256, 256>>>(W, Wa1, 0);
    pack_k<<<(256 * XPW + 255) / 256, 256>>>(U, Ua1, 1);
    initmask_k<<<NROWS / 256, 256>>>(maskp);

    // embedding: g_hseq = permute(x) @ W_emb + b_emb
    gemm_k<<<dim3(2, 256), 256>>>(x, W_emb, b_emb, 256, 0);

    for (int d = 0; d < NDEPTH; d++) {
        gemm_k<<<dim3(7, 256), 256>>>(nullptr, nullptr, nullptr, XPW, 1);
        lnx_k<<<NROWS, 256>>>(gammas, betas);
        scan_k<<<128, 512>>>(b, ba1, Wa2, ba2,
                             gammas + H3, betas + H3,
                             out, out_size, d, d & 1);
    }

    copyout_k<<<64, 256>>>(out, out_size);
}

// round 14
// speedup vs baseline: 1.0216x; 1.0216x over previous
#include <cuda_runtime.h>
#include <math.h>
#include <stdint.h>

// ---------------------------------------------------------------------------
// Problem constants (fixed by setup_inputs)
// ---------------------------------------------------------------------------
#define Bn 64
#define Ln 512
#define Hn 256
#define H3 768
#define An 128
#define NDEPTH 4
#define NROWS (Ln * Bn)          /* 32768, t-major: row = t*Bn + b */
#define XPW 896                  /* 768 (gru proj) + 128 (action proj) */
#define OUT_ACT 16384            /* Bn*Hn */
#define OUT_POL 147456           /* OUT_ACT + Bn*NDEPTH*Ln */

#define CSIZE 8                  /* cluster size */
#define CCOLS 96                 /* gru columns per CTA (768/8) */

// ---------------------------------------------------------------------------
// Static scratch
// ---------------------------------------------------------------------------
__device__ float g_hseq[NROWS * Hn];                    // 32 MB
__device__ float g_xpz[(size_t)NROWS * XPW];            // 112 MB
__device__ float g_wpack[256 * XPW];                    // [W | W_action_1], [k][896]
__device__ float g_upack[H3 * Hn];                      // U transposed: [c][k]
__device__ float g_axz[(size_t)NROWS * An];             // hprev @ Ua1 (16 MB)
__device__ unsigned char g_maskD[NDEPTH + 1][NROWS];    // per-depth input masks

// ---------------------------------------------------------------------------
// PTX helpers (cluster / DSMEM)
// ---------------------------------------------------------------------------
__device__ __forceinline__ uint32_t smem_u32(const void* p) {
    uint32_t a;
    asm("{ .reg .u64 t; cvta.to.shared.u64 t, %1; cvt.u32.u64 %0, t; }"
        : "=r"(a) : "l"(p));
    return a;
}
__device__ __forceinline__ uint32_t mapa_c(uint32_t a, uint32_t r) {
    uint32_t d;
    asm("mapa.shared::cluster.u32 %0, %1, %2;" : "=r"(d) : "r"(a), "r"(r));
    return d;
}
__device__ __forceinline__ void stc64(uint32_t a, unsigned long long v) {
    asm volatile("st.shared::cluster.b64 [%0], %1;" :: "r"(a), "l"(v) : "memory");
}
__device__ __forceinline__ void carrive() {
    asm volatile("barrier.cluster.arrive.aligned;" ::: "memory");
}
__device__ __forceinline__ void cwait() {
    asm volatile("barrier.cluster.wait.aligned;" ::: "memory");
}
__device__ __forceinline__ void cluster_sync() { carrive(); cwait(); }
__device__ __forceinline__ uint32_t ctarank() {
    uint32_t r; asm("mov.u32 %0, %%cluster_ctarank;" : "=r"(r)); return r;
}

// ---------------------------------------------------------------------------
// Pack [W(256x768) | Wa1(256x128)] -> g_wpack [k][896]
// ---------------------------------------------------------------------------
__global__ void pack_k(const float* __restrict__ Wm, const float* __restrict__ Wa)
{
    int i = blockIdx.x * blockDim.x + threadIdx.x;
    if (i < 256 * XPW) {
        int k = i / XPW, c = i % XPW;
        g_wpack[i] = (c < H3) ? Wm[k * H3 + c] : Wa[k * An + (c - H3)];
    }
}

// U (256x768) -> g_upack transposed [c][k]
__global__ void packu_k(const float* __restrict__ U)
{
    int i = blockIdx.x * blockDim.x + threadIdx.x;
    if (i < 256 * H3) {
        int k = i / H3, c = i % H3;
        g_upack[(size_t)c * 256 + k] = U[i];
    }
}

// mask input (B, L) 4-byte scalars -> t-major depth-0 mask
__global__ void initmask_k(const int* __restrict__ m)
{
    int i = blockIdx.x * blockDim.x + threadIdx.x;
    if (i < NROWS) {
        int t = i >> 6, b = i & 63;
        g_maskD[0][i] = (m[b * Ln + t] != 0) ? 1 : 0;
    }
}

// ---------------------------------------------------------------------------
// GEMM: C[32768 x N] = A[32768 x 256] @ B[256 x N] (+ bias)
// mode 0: A = x (permuted b-major -> t-major), B = W_emb, C = g_hseq
// mode 1: A = g_hseq, B = g_wpack, C = g_xpz
// mode 2: A = g_hseq shifted by -64 rows (t-1; t=0 -> zeros), B = Ua1, C = g_axz
// ---------------------------------------------------------------------------
__global__ void __launch_bounds__(256) gemm_k(
    const float* __restrict__ Aex, const float* __restrict__ Bex,
    const float* __restrict__ bias, int N, int mode)
{
    const float* __restrict__ A = (mode == 0) ? Aex : g_hseq;
    const float* __restrict__ B = (mode == 1) ? g_wpack : Bex;
    float* __restrict__ C = (mode == 0) ? g_hseq : ((mode == 1) ? g_xpz : g_axz);

    __shared__ __align__(16) float As[16][132];
    __shared__ __align__(16) float Bs[16][128];

    const int tid = threadIdx.x;
    const int bx = blockIdx.x, by = blockIdx.y;
    const int tx = tid & 15, ty = tid >> 4;

    float acc[8][8];
#pragma unroll
    for (int i = 0; i < 8; i++)
#pragma unroll
        for (int j = 0; j < 8; j++) acc[i][j] = 0.0f;

    const int ar  = tid & 127;
    const int akh = (tid >> 7) * 8;
    const int brow = tid >> 4;
    const int bcol = (tid & 15) * 8;

    const int m = by * 128 + ar;
    long arow; bool av = true;
    if (mode == 0)      arow = (long)(m & 63) * Ln + (m >> 6);
    else if (mode == 1) arow = m;
    else { arow = m - Bn; av = (m >= Bn); }

    for (int kt = 0; kt < 256; kt += 16) {
        float4 a0 = make_float4(0.f,0.f,0.f,0.f), a1 = a0;
        if (av) {
            const float* ap = A + arow * 256 + kt + akh;
            a0 = *(const float4*)ap;
            a1 = *(const float4*)(ap + 4);
        }
        As[akh + 0][ar] = a0.x; As[akh + 1][ar] = a0.y;
        As[akh + 2][ar] = a0.z; As[akh + 3][ar] = a0.w;
        As[akh + 4][ar] = a1.x; As[akh + 5][ar] = a1.y;
        As[akh + 6][ar] = a1.z; As[akh + 7][ar] = a1.w;

        const float* bp = B + (long)(kt + brow) * N + bx * 128 + bcol;
        *(float4*)&Bs[brow][bcol]     = *(const float4*)bp;
        *(float4*)&Bs[brow][bcol + 4] = *(const float4*)(bp + 4);
        __syncthreads();

#pragma unroll
        for (int kk = 0; kk < 16; kk++) {
            float a8[8], b8[8];
            *(float4*)&a8[0] = *(const float4*)&As[kk][ty * 8];
            *(float4*)&a8[4] = *(const float4*)&As[kk][ty * 8 + 4];
            *(float4*)&b8[0] = *(const float4*)&Bs[kk][tx * 8];
            *(float4*)&b8[4] = *(const float4*)&Bs[kk][tx * 8 + 4];
#pragma unroll
            for (int i = 0; i < 8; i++)
#pragma unroll
                for (int j = 0; j < 8; j++)
                    acc[i][j] = fmaf(a8[i], b8[j], acc[i][j]);
        }
        __syncthreads();
    }

    float bv[8];
#pragma unroll
    for (int j = 0; j < 8; j++)
        bv[j] = bias ? bias[bx * 128 + tx * 8 + j] : 0.0f;

#pragma unroll
    for (int i = 0; i < 8; i++) {
        long row = by * 128 + ty * 8 + i;
        float* cp = C + row * N + bx * 128 + tx * 8;
        float4 o0, o1;
        o0.x = acc[i][0] + bv[0]; o0.y = acc[i][1] + bv[1];
        o0.z = acc[i][2] + bv[2]; o0.w = acc[i][3] + bv[3];
        o1.x = acc[i][4] + bv[4]; o1.y = acc[i][5] + bv[5];
        o1.z = acc[i][6] + bv[6]; o1.w = acc[i][7] + bv[7];
        *(float4*)cp       = o0;
        *(float4*)(cp + 4) = o1;
    }
}

// ---------------------------------------------------------------------------
// Row LayerNorm of g_xpz[:, 0:768] in place (gamma0/beta0). 1 block/row.
// ---------------------------------------------------------------------------
__global__ void __launch_bounds__(256) lnx_k(const float* __restrict__ gam,
                                             const float* __restrict__ bet)
{
    long row = blockIdx.x;
    float* p = g_xpz + row * XPW;
    int tid = threadIdx.x;
    float v0 = p[tid], v1 = p[tid + 256], v2 = p[tid + 512];
    float s = v0 + v1 + v2;
    float q = v0 * v0 + v1 * v1 + v2 * v2;

    __shared__ float rs[8], rq[8], st[2];
#pragma unroll
    for (int off = 16; off; off >>= 1) {
        s += __shfl_down_sync(0xffffffffu, s, off);
        q += __shfl_down_sync(0xffffffffu, q, off);
    }
    if ((tid & 31) == 0) { rs[tid >> 5] = s; rq[tid >> 5] = q; }
    __syncthreads();
    if (tid == 0) {
        float S = 0.f, Q = 0.f;
#pragma unroll
        for (int i = 0; i < 8; i++) { S += rs[i]; Q += rq[i]; }
        float mean = S * (1.0f / 768.0f);
        float var  = Q * (1.0f / 768.0f) - mean * mean;
        st[0] = mean;
        st[1] = rsqrtf(var + 1e-5f);
    }
    __syncthreads();
    float mean = st[0], r = st[1];
    p[tid]       = (v0 - mean) * r * gam[tid]       + bet[tid];
    p[tid + 256] = (v1 - mean) * r * gam[tid + 256] + bet[tid + 256];
    p[tid + 512] = (v2 - mean) * r * gam[tid + 512] + bet[tid + 512];
}

// ---------------------------------------------------------------------------
// Cluster scan v4: 16 clusters x 8 CTAs x 512 threads; cluster owns 4 batch
// rows. Rank owns contiguous U cols [rank*96, rank*96+96), in REGISTERS.
// Per step: local GEMV -> broadcast z slices (double-buffered) -> ONE cluster
// barrier -> every CTA computes LN stats + ALL gates redundantly -> h local.
// No action subnetwork here (deferred to act pass).
// ---------------------------------------------------------------------------
__global__ void __launch_bounds__(512, 1) __cluster_dims__(CSIZE, 1, 1)
scan_k(const float* __restrict__ bias3,
       const float* __restrict__ gam1, const float* __restrict__ bet1,
       int dep)
{
    __shared__ __align__(16) float hsf[1024];     // h: [row][k]
    __shared__ __align__(16) float part[1536];    // split-k: [q][col] float4(rows)
    __shared__ __align__(16) float zf[2 * 3072];  // z: [parity][col] float4(rows)
    __shared__ float wred[16 * 8];
    __shared__ float stats[8];
    __shared__ float gc[H3], ge[H3], gb[H3];

    const int tid = threadIdx.x;
    const uint32_t rank = ctarank();
    const int bbase = (blockIdx.x / CSIZE) * 4;
    const uint32_t zf32 = smem_u32(zf);

    const unsigned char* __restrict__ min_ = g_maskD[dep];

    // U registers: 384 GEMV threads = 96 cols x 4 k-quarters, 16 float4 each
    const int cl = tid % CCOLS;
    const int gq = tid / CCOLS;
    float4 uq[16];
    if (tid < 384) {
        const float4* up = (const float4*)(g_upack +
                           ((size_t)((int)rank * CCOLS + cl) * 256 + gq * 64));
#pragma unroll
        for (int i = 0; i < 16; i++) uq[i] = up[i];
    }
    for (int i = tid; i < H3; i += 512) {
        gc[i] = gam1[i]; ge[i] = bet1[i]; gb[i] = bias3[i];
    }
    hsf[tid] = 0.0f; hsf[tid + 512] = 0.0f;

    // gate identity: row r = tid>>7, cols c2 and c2+128
    const int r  = tid >> 7;
    const int c2 = tid & 127;
    const int c3 = c2 + 128;
    const int myrow = bbase + r;
    float hprev0 = 0.0f, hprev1 = 0.0f;
    __syncthreads();
    cluster_sync();   // h=0 everywhere; smem ready

    for (int t = 0; t < Ln; t++) {
        const int p = t & 1;
        // ---- prefetch xp + mask (hidden under GEMV + barrier) ----
        long base = (long)(t * Bn + myrow) * XPW;
        float xp00 = g_xpz[base + c2];
        float xp01 = g_xpz[base + c2 + 256];
        float xp02 = g_xpz[base + c2 + 512];
        float xp10 = g_xpz[base + c3];
        float xp11 = g_xpz[base + c3 + 256];
        float xp12 = g_xpz[base + c3 + 512];
        int mt = min_[t * Bn + myrow];

        // ---- GEMV: z_partial for own 96 cols, 4 rows (local h) ----
        if (tid < 384) {
            float a0 = 0.f, a1 = 0.f, a2 = 0.f, a3 = 0.f;
            const float4* h0 = (const float4*)(hsf + gq * 64);
            const float4* h1 = (const float4*)(hsf + 256 + gq * 64);
            const float4* h2 = (const float4*)(hsf + 512 + gq * 64);
            const float4* h3 = (const float4*)(hsf + 768 + gq * 64);
#pragma unroll
            for (int i = 0; i < 16; i++) {
                float4 u4 = uq[i];
                float4 v0 = h0[i], v1 = h1[i], v2 = h2[i], v3 = h3[i];
                a0 = fmaf(u4.x, v0.x, a0); a0 = fmaf(u4.y, v0.y, a0);
                a0 = fmaf(u4.z, v0.z, a0); a0 = fmaf(u4.w, v0.w, a0);
                a1 = fmaf(u4.x, v1.x, a1); a1 = fmaf(u4.y, v1.y, a1);
                a1 = fmaf(u4.z, v1.z, a1); a1 = fmaf(u4.w, v1.w, a1);
                a2 = fmaf(u4.x, v2.x, a2); a2 = fmaf(u4.y, v2.y, a2);
                a2 = fmaf(u4.z, v2.z, a2); a2 = fmaf(u4.w, v2.w, a2);
                a3 = fmaf(u4.x, v3.x, a3); a3 = fmaf(u4.y, v3.y, a3);
                a3 = fmaf(u4.z, v3.z, a3); a3 = fmaf(u4.w, v3.w, a3);
            }
            ((float4*)part)[gq * CCOLS + cl] = make_float4(a0, a1, a2, a3);
        }
        __syncthreads();

        // ---- split-k reduce + broadcast z slice to all 8 ranks ----
        if (tid < CCOLS) {
            const float4* pp = (const float4*)part;
            float4 v0 = pp[tid], v1 = pp[CCOLS + tid],
                   v2 = pp[2 * CCOLS + tid], v3 = pp[3 * CCOLS + tid];
            float zx = v0.x + v1.x + v2.x + v3.x;
            float zy = v0.y + v1.y + v2.y + v3.y;
            float zz = v0.z + v1.z + v2.z + v3.z;
            float zw = v0.w + v1.w + v2.w + v3.w;
            unsigned long long lo, hi;
            asm("mov.b64 %0, {%1,%2};" : "=l"(lo) : "f"(zx), "f"(zy));
            asm("mov.b64 %0, {%1,%2};" : "=l"(hi) : "f"(zz), "f"(zw));
            uint32_t off = zf32 + (uint32_t)((p * 3072 + ((int)rank * CCOLS + tid) * 4) * 4);
#pragma unroll
            for (uint32_t ii = 0; ii < CSIZE; ii++) {
                uint32_t pa = mapa_c(off, ii);
                stc64(pa, lo); stc64(pa + 8, hi);
            }
        }
        carrive();
        cwait();   // single rendezvous: all z slices visible

        // ---- LN stats (local, all 512 threads) ----
        const float4* zf4 = (const float4*)(zf + p * 3072);
        float4 zv = zf4[tid];
        float Sx = zv.x, Sy = zv.y, Sz = zv.z, Sw = zv.w;
        float Qx = zv.x * zv.x, Qy = zv.y * zv.y, Qz = zv.z * zv.z, Qw = zv.w * zv.w;
        if (tid < 256) {
            float4 w2 = zf4[512 + tid];
            Sx += w2.x; Sy += w2.y; Sz += w2.z; Sw += w2.w;
            Qx += w2.x * w2.x; Qy += w2.y * w2.y; Qz += w2.z * w2.z; Qw += w2.w * w2.w;
        }
#pragma unroll
        for (int o = 16; o; o >>= 1) {
            Sx += __shfl_xor_sync(0xffffffffu, Sx, o);
            Sy += __shfl_xor_sync(0xffffffffu, Sy, o);
            Sz += __shfl_xor_sync(0xffffffffu, Sz, o);
            Sw += __shfl_xor_sync(0xffffffffu, Sw, o);
            Qx += __shfl_xor_sync(0xffffffffu, Qx, o);
            Qy += __shfl_xor_sync(0xffffffffu, Qy, o);
            Qz += __shfl_xor_sync(0xffffffffu, Qz, o);
            Qw += __shfl_xor_sync(0xffffffffu, Qw, o);
        }
        if ((tid & 31) == 0) {
            int w = tid >> 5;
            wred[w * 8 + 0] = Sx; wred[w * 8 + 1] = Sy;
            wred[w * 8 + 2] = Sz; wred[w * 8 + 3] = Sw;
            wred[w * 8 + 4] = Qx; wred[w * 8 + 5] = Qy;
            wred[w * 8 + 6] = Qz; wred[w * 8 + 7] = Qw;
        }
        __syncthreads();
        if (tid < 8) {
            float acc = 0.f;
#pragma unroll
            for (int w = 0; w < 16; w++) acc += wred[w * 8 + tid];
            float qv = __shfl_sync(0x000000ffu, acc, tid + 4);
            if (tid < 4) {
                float mean = acc * (1.0f / 768.0f);
                float var  = qv * (1.0f / 768.0f) - mean * mean;
                stats[2 * tid] = mean;
                stats[2 * tid + 1] = rsqrtf(var + 1e-5f);
            }
        }
        __syncthreads();

        // ---- gates (redundant in every CTA; 2 cols x 1 row per thread) ----
        {
            const float* zfp = zf + p * 3072;
            float mean = stats[2 * r], rstd = stats[2 * r + 1];

            float z0 = zfp[c2 * 4 + r];
            float z1 = zfp[(c2 + 256) * 4 + r];
            float z2 = zfp[(c2 + 512) * 4 + r];
            float hp0 = (z0 - mean) * rstd * gc[c2]       + ge[c2];
            float hp1 = (z1 - mean) * rstd * gc[c2 + 256] + ge[c2 + 256];
            float hp2 = (z2 - mean) * rstd * gc[c2 + 512] + ge[c2 + 512];
            float rg = 1.0f / (1.0f + expf(-(xp00 + hp0 + gb[c2])));
            float zg = 1.0f / (1.0f + expf(-(xp01 + hp1 + gb[c2 + 256])));
            float hh = tanhf(xp02 + rg * hp2 + gb[c2 + 512]);
            float hn = zg * hprev0 + (1.0f - zg) * hh;
            float ho0 = mt ? hn : hprev0;
            hprev0 = ho0;
            hsf[r * 256 + c2] = ho0;

            z0 = zfp[c3 * 4 + r];
            z1 = zfp[(c3 + 256) * 4 + r];
            z2 = zfp[(c3 + 512) * 4 + r];
            hp0 = (z0 - mean) * rstd * gc[c3]       + ge[c3];
            hp1 = (z1 - mean) * rstd * gc[c3 + 256] + ge[c3 + 256];
            hp2 = (z2 - mean) * rstd * gc[c3 + 512] + ge[c3 + 512];
            rg = 1.0f / (1.0f + expf(-(xp10 + hp0 + gb[c3])));
            zg = 1.0f / (1.0f + expf(-(xp11 + hp1 + gb[c3 + 256])));
            hh = tanhf(xp12 + rg * hp2 + gb[c3 + 512]);
            hn = zg * hprev1 + (1.0f - zg) * hh;
            float ho1 = mt ? hn : hprev1;
            hprev1 = ho1;
            hsf[r * 256 + c3] = ho1;

            if (rank == 0) {
                long gbase = (long)(t * Bn + myrow) * Hn;
                g_hseq[gbase + c2] = ho0;
                g_hseq[gbase + c3] = ho1;
            }
        }
        __syncthreads();   // hsf(t) ready for next GEMV (local only)
    }
    cluster_sync();
}

// ---------------------------------------------------------------------------
// Action pass (per depth, after scan): logits/policy/action + next mask.
// a = tanh(xa + axz + ba1); l = a @ Wa2 + ba2.  Block = 2 rows x 128 threads.
// ---------------------------------------------------------------------------
__global__ void __launch_bounds__(256) act2_k(
    const float* __restrict__ ba1, const float* __restrict__ wa2,
    const float* __restrict__ ba2,
    float* __restrict__ out, int out_size, int dep)
{
    __shared__ float red[2][4][2];
    const int rr = threadIdx.x >> 7;
    const int j  = threadIdx.x & 127;
    const long row = (long)blockIdx.x * 2 + rr;

    float a = tanhf(g_xpz[row * XPW + H3 + j] + g_axz[row * An + j] + ba1[j]);
    float p0 = a * wa2[2 * j];
    float p1 = a * wa2[2 * j + 1];
#pragma unroll
    for (int o = 16; o; o >>= 1) {
        p0 += __shfl_xor_sync(0xffffffffu, p0, o);
        p1 += __shfl_xor_sync(0xffffffffu, p1, o);
    }
    int w = (threadIdx.x >> 5) & 3;
    if ((threadIdx.x & 31) == 0) { red[rr][w][0] = p0; red[rr][w][1] = p1; }
    __syncthreads();
    if (j == 0) {
        float l0 = ba2[0], l1 = ba2[1];
#pragma unroll
        for (int q = 0; q < 4; q++) { l0 += red[rr][q][0]; l1 += red[rr][q][1]; }
        int t = (int)(row >> 6), b = (int)(row & 63);
        int m = g_maskD[dep][row];
        int act = (l1 > l0) && m;      // pol1>pol0 <=> l1>l0 (softmax monotone)
        float mx = fmaxf(l0, l1);
        float e0 = expf(l0 - mx), e1 = expf(l1 - mx);
        float inv = 1.0f / (e0 + e1);
        int ai = OUT_ACT + (b * NDEPTH + dep) * Ln + t;
        if (ai < out_size) out[ai] = (float)act;
        int pi = OUT_POL + ((b * NDEPTH + dep) * Ln + t) * 2;
        if (pi + 1 < out_size) { out[pi] = e0 * inv; out[pi + 1] = e1 * inv; }
        g_maskD[dep + 1][row] = (unsigned char)act;
    }
}

// ---------------------------------------------------------------------------
// output = h_seq[-1] (t = 511), (B, H)
// ---------------------------------------------------------------------------
__global__ void copyout_k(float* __restrict__ out, int out_size)
{
    int i = blockIdx.x * blockDim.x + threadIdx.x;
    if (i < Bn * Hn && i < out_size)
        out[i] = g_hseq[(long)(511 * Bn + (i >> 8)) * Hn + (i & 255)];
}

// ---------------------------------------------------------------------------
// launch
// ---------------------------------------------------------------------------
extern "C" void kernel_launch(void* const* d_in, const int* in_sizes, int n_in,
                              void* d_out, int out_size)
{
    const float* x      = (const float*)d_in[0];
    const int*   maskp  = (const int*)  d_in[1];
    const float* W_emb  = (const float*)d_in[2];
    const float* b_emb  = (const float*)d_in[3];
    const float* W      = (const float*)d_in[4];
    const float* U      = (const float*)d_in[5];
    const float* b      = (const float*)d_in[6];
    const float* Wa1    = (const float*)d_in[7];
    const float* Ua1    = (const float*)d_in[8];
    const float* ba1    = (const float*)d_in[9];
    const float* Wa2    = (const float*)d_in[10];
    const float* ba2    = (const float*)d_in[11];
    const float* gammas = (const float*)d_in[12];
    const float* betas  = (const float*)d_in[13];
    float* out = (float*)d_out;

    pack_k<<<(256 * XPW + 255) / 256, 256>>>(W, Wa1);
    packu_k<<<(256 * H3 + 255) / 256, 256>>>(U);
    initmask_k<<<NROWS / 256, 256>>>(maskp);

    // embedding: g_hseq = permute(x) @ W_emb + b_emb
    gemm_k<<<dim3(2, 256), 256>>>(x, W_emb, b_emb, 256, 0);

    for (int d = 0; d < NDEPTH; d++) {
        // g_xpz = g_hseq @ [W | Wa1], then LN(cols 0..767)
        gemm_k<<<dim3(7, 256), 256>>>(nullptr, nullptr, nullptr, XPW, 1);
        lnx_k<<<NROWS, 256>>>(gammas, betas);
        // recurrence (writes g_hseq)
        scan_k<<<128, 512>>>(b, gammas + H3, betas + H3, d);
        // action pass: axz = hprev @ Ua1, then logits/policy/mask
        gemm_k<<<dim3(1, 256), 256>>>(nullptr, Ua1, nullptr, An, 2);
        act2_k<<<NROWS / 2, 256>>>(ba1, Wa2, ba2, out, out_size, d);
    }

    copyout_k<<<64, 256>>>(out, out_size);
}

// round 16
// speedup vs baseline: 1.0511x; 1.0289x over previous
#include <cuda_runtime.h>
#include <math.h>
#include <stdint.h>

// ---------------------------------------------------------------------------
// Problem constants (fixed by setup_inputs)
// ---------------------------------------------------------------------------
#define Bn 64
#define Ln 512
#define Hn 256
#define H3 768
#define An 128
#define NDEPTH 4
#define NROWS (Ln * Bn)          /* 32768, t-major: row = t*Bn + b */
#define XPW 896                  /* 768 (gru proj) + 128 (action proj) */
#define OUT_ACT 16384            /* Bn*Hn */
#define OUT_POL 147456           /* OUT_ACT + Bn*NDEPTH*Ln */

#define CSIZE 8                  /* cluster size */
#define CCOLS 96                 /* gru columns per CTA (768/8) */

// Dynamic smem layout for scan (float offsets)
#define SMO_HS    0              /* h: [row][k] 4*256 = 1024 */
#define SMO_PART  1024           /* split-k: [q][col] float4(rows) = 1536 */
#define SMO_ZF    2560           /* z: [parity][col] float4(rows) = 6144 */
#define SMO_WRED  8704           /* 12 warps * 8 ch = 96 */
#define SMO_WREDX 8800           /* 16 warps * 2 ch = 32 */
#define SMO_STATS 8832           /* 8 */
#define SMO_STATSX 8840          /* 8 */
#define SMO_GC    8848           /* gamma1 768 */
#define SMO_GE    9616           /* beta1 768 */
#define SMO_GB    10384          /* bias 768 */
#define SMO_XG    11152          /* gamma0 768 */
#define SMO_XB    11920          /* beta0 768 */
#define SMO_TOT   12688
#define SCAN_SMEM (SMO_TOT * 4)  /* 50752 bytes */

// ---------------------------------------------------------------------------
// Static scratch
// ---------------------------------------------------------------------------
__device__ float g_hseq[NROWS * Hn];                    // 32 MB
__device__ float g_xpz[(size_t)NROWS * XPW];            // 112 MB (raw, un-LN'd)
__device__ float g_wpack[256 * XPW];                    // [W | W_action_1], [k][896]
__device__ float g_upack[H3 * Hn];                      // U transposed: [c][k]
__device__ float g_axz[(size_t)NROWS * An];             // hprev @ Ua1
__device__ unsigned char g_maskD[NDEPTH + 1][NROWS];    // per-depth input masks

// ---------------------------------------------------------------------------
// PTX helpers (cluster / DSMEM)
// ---------------------------------------------------------------------------
__device__ __forceinline__ uint32_t smem_u32(const void* p) {
    uint32_t a;
    asm("{ .reg .u64 t; cvta.to.shared.u64 t, %1; cvt.u32.u64 %0, t; }"
        : "=r"(a) : "l"(p));
    return a;
}
__device__ __forceinline__ uint32_t mapa_c(uint32_t a, uint32_t r) {
    uint32_t d;
    asm("mapa.shared::cluster.u32 %0, %1, %2;" : "=r"(d) : "r"(a), "r"(r));
    return d;
}
__device__ __forceinline__ void stc64(uint32_t a, unsigned long long v) {
    asm volatile("st.shared::cluster.b64 [%0], %1;" :: "r"(a), "l"(v) : "memory");
}
__device__ __forceinline__ void carrive() {
    asm volatile("barrier.cluster.arrive.aligned;" ::: "memory");
}
__device__ __forceinline__ void cwait() {
    asm volatile("barrier.cluster.wait.aligned;" ::: "memory");
}
__device__ __forceinline__ void cluster_sync() { carrive(); cwait(); }
__device__ __forceinline__ uint32_t ctarank() {
    uint32_t r; asm("mov.u32 %0, %%cluster_ctarank;" : "=r"(r)); return r;
}
__device__ __forceinline__ float fsig(float x) {
    return __fdividef(1.0f, 1.0f + __expf(-x));
}
__device__ __forceinline__ float ftanh(float x) {
    return __fdividef(2.0f, 1.0f + __expf(-2.0f * x)) - 1.0f;
}

// ---------------------------------------------------------------------------
// prep: wpack + upack-transpose + mask init in ONE launch (keeps scan_k at
// the ncu-captured launch slot).
// ---------------------------------------------------------------------------
#define PREP_W (256 * XPW)                 /* 229376 */
#define PREP_U (256 * H3)                  /* 196608 */
#define PREP_TOT (PREP_W + PREP_U + NROWS) /* 458752 */

__global__ void prep_k(const float* __restrict__ Wm, const float* __restrict__ Wa,
                       const float* __restrict__ U,  const int* __restrict__ m)
{
    int i = blockIdx.x * blockDim.x + threadIdx.x;
    if (i < PREP_W) {
        int k = i / XPW, c = i % XPW;
        g_wpack[i] = (c < H3) ? Wm[k * H3 + c] : Wa[k * An + (c - H3)];
    } else if (i < PREP_W + PREP_U) {
        int j = i - PREP_W;
        int k = j / H3, c = j % H3;
        g_upack[(size_t)c * 256 + k] = U[j];
    } else if (i < PREP_TOT) {
        int j = i - PREP_W - PREP_U;
        int t = j >> 6, b = j & 63;
        g_maskD[0][j] = (m[b * Ln + t] != 0) ? 1 : 0;
    }
}

// ---------------------------------------------------------------------------
// GEMM: C[32768 x N] = A[32768 x 256] @ B[256 x N] (+ bias)
// mode 0: A = x (permuted b-major -> t-major), B = W_emb, C = g_hseq
// mode 1: A = g_hseq, B = g_wpack, C = g_xpz (raw)
// mode 2: A = g_hseq shifted by -64 rows (t-1; t=0 -> zeros), B = Ua1, C = g_axz
// ---------------------------------------------------------------------------
__global__ void __launch_bounds__(256) gemm_k(
    const float* __restrict__ Aex, const float* __restrict__ Bex,
    const float* __restrict__ bias, int N, int mode)
{
    const float* __restrict__ A = (mode == 0) ? Aex : g_hseq;
    const float* __restrict__ B = (mode == 1) ? g_wpack : Bex;
    float* __restrict__ C = (mode == 0) ? g_hseq : ((mode == 1) ? g_xpz : g_axz);

    __shared__ __align__(16) float As[16][132];
    __shared__ __align__(16) float Bs[16][128];

    const int tid = threadIdx.x;
    const int bx = blockIdx.x, by = blockIdx.y;
    const int tx = tid & 15, ty = tid >> 4;

    float acc[8][8];
#pragma unroll
    for (int i = 0; i < 8; i++)
#pragma unroll
        for (int j = 0; j < 8; j++) acc[i][j] = 0.0f;

    const int ar  = tid & 127;
    const int akh = (tid >> 7) * 8;
    const int brow = tid >> 4;
    const int bcol = (tid & 15) * 8;

    const int m = by * 128 + ar;
    long arow; bool av = true;
    if (mode == 0)      arow = (long)(m & 63) * Ln + (m >> 6);
    else if (mode == 1) arow = m;
    else { arow = m - Bn; av = (m >= Bn); }

    for (int kt = 0; kt < 256; kt += 16) {
        float4 a0 = make_float4(0.f,0.f,0.f,0.f), a1 = a0;
        if (av) {
            const float* ap = A + arow * 256 + kt + akh;
            a0 = *(const float4*)ap;
            a1 = *(const float4*)(ap + 4);
        }
        As[akh + 0][ar] = a0.x; As[akh + 1][ar] = a0.y;
        As[akh + 2][ar] = a0.z; As[akh + 3][ar] = a0.w;
        As[akh + 4][ar] = a1.x; As[akh + 5][ar] = a1.y;
        As[akh + 6][ar] = a1.z; As[akh + 7][ar] = a1.w;

        const float* bp = B + (long)(kt + brow) * N + bx * 128 + bcol;
        *(float4*)&Bs[brow][bcol]     = *(const float4*)bp;
        *(float4*)&Bs[brow][bcol + 4] = *(const float4*)(bp + 4);
        __syncthreads();

#pragma unroll
        for (int kk = 0; kk < 16; kk++) {
            float a8[8], b8[8];
            *(float4*)&a8[0] = *(const float4*)&As[kk][ty * 8];
            *(float4*)&a8[4] = *(const float4*)&As[kk][ty * 8 + 4];
            *(float4*)&b8[0] = *(const float4*)&Bs[kk][tx * 8];
            *(float4*)&b8[4] = *(const float4*)&Bs[kk][tx * 8 + 4];
#pragma unroll
            for (int i = 0; i < 8; i++)
#pragma unroll
                for (int j = 0; j < 8; j++)
                    acc[i][j] = fmaf(a8[i], b8[j], acc[i][j]);
        }
        __syncthreads();
    }

    float bv[8];
#pragma unroll
    for (int j = 0; j < 8; j++)
        bv[j] = bias ? bias[bx * 128 + tx * 8 + j] : 0.0f;

#pragma unroll
    for (int i = 0; i < 8; i++) {
        long row = by * 128 + ty * 8 + i;
        float* cp = C + row * N + bx * 128 + tx * 8;
        float4 o0, o1;
        o0.x = acc[i][0] + bv[0]; o0.y = acc[i][1] + bv[1];
        o0.z = acc[i][2] + bv[2]; o0.w = acc[i][3] + bv[3];
        o1.x = acc[i][4] + bv[4]; o1.y = acc[i][5] + bv[5];
        o1.z = acc[i][6] + bv[6]; o1.w = acc[i][7] + bv[7];
        *(float4*)cp       = o0;
        *(float4*)(cp + 4) = o1;
    }
}

// ---------------------------------------------------------------------------
// Cluster scan v5: 16 clusters x 8 CTAs x 512 threads; cluster owns 4 batch
// rows. Rank owns U cols [rank*96, rank*96+96) in REGISTERS. Per step:
// local GEMV -> z broadcast (parity double-buffered) -> ONE cluster barrier
// -> redundant LN stats (z AND raw xp, fused LN) + gates -> h local.
// ---------------------------------------------------------------------------
__global__ void __launch_bounds__(512, 1) __cluster_dims__(CSIZE, 1, 1)
scan_k(const float* __restrict__ bias3,
       const float* __restrict__ gam0, const float* __restrict__ bet0,
       const float* __restrict__ gam1, const float* __restrict__ bet1,
       int dep)
{
    extern __shared__ __align__(16) float sm[];
    float* hsf   = sm + SMO_HS;
    float* part  = sm + SMO_PART;
    float* zf    = sm + SMO_ZF;
    float* wred  = sm + SMO_WRED;
    float* wredx = sm + SMO_WREDX;
    float* stats = sm + SMO_STATS;
    float* statsx= sm + SMO_STATSX;
    float* gc    = sm + SMO_GC;
    float* ge    = sm + SMO_GE;
    float* gb    = sm + SMO_GB;
    float* xg    = sm + SMO_XG;
    float* xb    = sm + SMO_XB;

    const int tid = threadIdx.x;
    const uint32_t rank = ctarank();
    const int bbase = (blockIdx.x / CSIZE) * 4;
    const uint32_t zf32 = smem_u32(zf);

    const unsigned char* __restrict__ min_ = g_maskD[dep];

    // U registers: 384 GEMV threads = 96 cols x 4 k-quarters, 16 float4 each
    const int cl = tid % CCOLS;
    const int gq = tid / CCOLS;
    float4 uq[16];
    if (tid < 384) {
        const float4* up = (const float4*)(g_upack +
                           ((size_t)((int)rank * CCOLS + cl) * 256 + gq * 64));
#pragma unroll
        for (int i = 0; i < 16; i++) uq[i] = up[i];
    }
    for (int i = tid; i < H3; i += 512) {
        gc[i] = gam1[i]; ge[i] = bet1[i]; gb[i] = bias3[i];
        xg[i] = gam0[i]; xb[i] = bet0[i];
    }
    hsf[tid] = 0.0f; hsf[tid + 512] = 0.0f;

    // gate identity: row r = tid>>7, cols c2 and c2+128
    const int r  = tid >> 7;
    const int c2 = tid & 127;
    const int c3 = c2 + 128;
    const int myrow = bbase + r;
    const int wp = tid >> 5;
    float hprev0 = 0.0f, hprev1 = 0.0f;
    __syncthreads();
    cluster_sync();   // h=0 + smem consts visible cluster-wide

    for (int t = 0; t < Ln; t++) {
        const int p = t & 1;
        // ---- prefetch raw xp + mask (hidden under GEMV) ----
        long base = (long)(t * Bn + myrow) * XPW;
        float xp00 = g_xpz[base + c2];
        float xp01 = g_xpz[base + c2 + 256];
        float xp02 = g_xpz[base + c2 + 512];
        float xp10 = g_xpz[base + c3];
        float xp11 = g_xpz[base + c3 + 256];
        float xp12 = g_xpz[base + c3 + 512];
        int mt = min_[t * Bn + myrow];

        // ---- GEMV: z_partial for own 96 cols, 4 rows (local h) ----
        if (tid < 384) {
            float a0 = 0.f, a1 = 0.f, a2 = 0.f, a3 = 0.f;
            const float4* h0 = (const float4*)(hsf + gq * 64);
            const float4* h1 = (const float4*)(hsf + 256 + gq * 64);
            const float4* h2 = (const float4*)(hsf + 512 + gq * 64);
            const float4* h3 = (const float4*)(hsf + 768 + gq * 64);
#pragma unroll
            for (int i = 0; i < 16; i++) {
                float4 u4 = uq[i];
                float4 v0 = h0[i], v1 = h1[i], v2 = h2[i], v3 = h3[i];
                a0 = fmaf(u4.x, v0.x, a0); a0 = fmaf(u4.y, v0.y, a0);
                a0 = fmaf(u4.z, v0.z, a0); a0 = fmaf(u4.w, v0.w, a0);
                a1 = fmaf(u4.x, v1.x, a1); a1 = fmaf(u4.y, v1.y, a1);
                a1 = fmaf(u4.z, v1.z, a1); a1 = fmaf(u4.w, v1.w, a1);
                a2 = fmaf(u4.x, v2.x, a2); a2 = fmaf(u4.y, v2.y, a2);
                a2 = fmaf(u4.z, v2.z, a2); a2 = fmaf(u4.w, v2.w, a2);
                a3 = fmaf(u4.x, v3.x, a3); a3 = fmaf(u4.y, v3.y, a3);
                a3 = fmaf(u4.z, v3.z, a3); a3 = fmaf(u4.w, v3.w, a3);
            }
            ((float4*)part)[gq * CCOLS + cl] = make_float4(a0, a1, a2, a3);
        }
        __syncthreads();

        // ---- split-k reduce + broadcast z slice; all threads: xp LN partials
        {
            // xp stats (fused LayerNorm of the input projection)
            float xs = xp00 + xp01 + xp02 + xp10 + xp11 + xp12;
            float xq = xp00*xp00 + xp01*xp01 + xp02*xp02
                     + xp10*xp10 + xp11*xp11 + xp12*xp12;
#pragma unroll
            for (int o = 16; o; o >>= 1) {
                xs += __shfl_xor_sync(0xffffffffu, xs, o);
                xq += __shfl_xor_sync(0xffffffffu, xq, o);
            }
            if ((tid & 31) == 0) { wredx[wp * 2] = xs; wredx[wp * 2 + 1] = xq; }
        }
        if (tid < CCOLS) {
            const float4* pp = (const float4*)part;
            float4 v0 = pp[tid], v1 = pp[CCOLS + tid],
                   v2 = pp[2 * CCOLS + tid], v3 = pp[3 * CCOLS + tid];
            float zx = v0.x + v1.x + v2.x + v3.x;
            float zy = v0.y + v1.y + v2.y + v3.y;
            float zz = v0.z + v1.z + v2.z + v3.z;
            float zw = v0.w + v1.w + v2.w + v3.w;
            unsigned long long lo, hi;
            asm("mov.b64 %0, {%1,%2};" : "=l"(lo) : "f"(zx), "f"(zy));
            asm("mov.b64 %0, {%1,%2};" : "=l"(hi) : "f"(zz), "f"(zw));
            uint32_t off = zf32 + (uint32_t)((p * 3072 + ((int)rank * CCOLS + tid) * 4) * 4);
#pragma unroll
            for (uint32_t ii = 0; ii < CSIZE; ii++) {
                uint32_t pa = mapa_c(off, ii);
                stc64(pa, lo); stc64(pa + 8, hi);
            }
        }
        carrive();
        cwait();   // single rendezvous: all z slices visible

        // ---- z LN stats (balanced: 384 threads x 2 float4) ----
        if (tid < 384) {
            const float4* zf4 = (const float4*)(zf + p * 3072);
            float4 a = zf4[tid];
            float4 bq = zf4[384 + tid];
            float Sx = a.x + bq.x, Sy = a.y + bq.y;
            float Sz = a.z + bq.z, Sw = a.w + bq.w;
            float Qx = a.x*a.x + bq.x*bq.x, Qy = a.y*a.y + bq.y*bq.y;
            float Qz = a.z*a.z + bq.z*bq.z, Qw = a.w*a.w + bq.w*bq.w;
#pragma unroll
            for (int o = 16; o; o >>= 1) {
                Sx += __shfl_xor_sync(0xffffffffu, Sx, o);
                Sy += __shfl_xor_sync(0xffffffffu, Sy, o);
                Sz += __shfl_xor_sync(0xffffffffu, Sz, o);
                Sw += __shfl_xor_sync(0xffffffffu, Sw, o);
                Qx += __shfl_xor_sync(0xffffffffu, Qx, o);
                Qy += __shfl_xor_sync(0xffffffffu, Qy, o);
                Qz += __shfl_xor_sync(0xffffffffu, Qz, o);
                Qw += __shfl_xor_sync(0xffffffffu, Qw, o);
            }
            if ((tid & 31) == 0) {
                wred[wp * 8 + 0] = Sx; wred[wp * 8 + 1] = Sy;
                wred[wp * 8 + 2] = Sz; wred[wp * 8 + 3] = Sw;
                wred[wp * 8 + 4] = Qx; wred[wp * 8 + 5] = Qy;
                wred[wp * 8 + 6] = Qz; wred[wp * 8 + 7] = Qw;
            }
        }
        __syncthreads();

        // ---- finalize stats: z (tid<4) and xp (tid 4..7, row tid-4) ----
        if (tid < 4) {
            float S = 0.f, Q = 0.f;
#pragma unroll
            for (int w = 0; w < 12; w++) { S += wred[w * 8 + tid]; Q += wred[w * 8 + 4 + tid]; }
            float mean = S * (1.0f / 768.0f);
            float var  = Q * (1.0f / 768.0f) - mean * mean;
            stats[2 * tid] = mean;
            stats[2 * tid + 1] = rsqrtf(var + 1e-5f);
        } else if (tid < 8) {
            int rr = tid - 4;
            float S = 0.f, Q = 0.f;
#pragma unroll
            for (int j = 0; j < 4; j++) {
                S += wredx[(4 * rr + j) * 2];
                Q += wredx[(4 * rr + j) * 2 + 1];
            }
            float mean = S * (1.0f / 768.0f);
            float var  = Q * (1.0f / 768.0f) - mean * mean;
            statsx[2 * rr] = mean;
            statsx[2 * rr + 1] = rsqrtf(var + 1e-5f);
        }
        __syncthreads();

        // ---- gates (redundant; 2 cols x 1 row per thread), fused xp LN ----
        {
            const float* zfp = zf + p * 3072;
            float mean = stats[2 * r], rstd = stats[2 * r + 1];
            float xm = statsx[2 * r], xrs = statsx[2 * r + 1];

            float xn0 = (xp00 - xm) * xrs * xg[c2]       + xb[c2];
            float xn1 = (xp01 - xm) * xrs * xg[c2 + 256] + xb[c2 + 256];
            float xn2 = (xp02 - xm) * xrs * xg[c2 + 512] + xb[c2 + 512];
            float z0 = zfp[c2 * 4 + r];
            float z1 = zfp[(c2 + 256) * 4 + r];
            float z2 = zfp[(c2 + 512) * 4 + r];
            float hp0 = (z0 - mean) * rstd * gc[c2]       + ge[c2];
            float hp1 = (z1 - mean) * rstd * gc[c2 + 256] + ge[c2 + 256];
            float hp2 = (z2 - mean) * rstd * gc[c2 + 512] + ge[c2 + 512];
            float rg = fsig(xn0 + hp0 + gb[c2]);
            float zg = fsig(xn1 + hp1 + gb[c2 + 256]);
            float hh = ftanh(xn2 + rg * hp2 + gb[c2 + 512]);
            float hn = zg * hprev0 + (1.0f - zg) * hh;
            float ho0 = mt ? hn : hprev0;
            hprev0 = ho0;
            hsf[r * 256 + c2] = ho0;

            xn0 = (xp10 - xm) * xrs * xg[c3]       + xb[c3];
            xn1 = (xp11 - xm) * xrs * xg[c3 + 256] + xb[c3 + 256];
            xn2 = (xp12 - xm) * xrs * xg[c3 + 512] + xb[c3 + 512];
            z0 = zfp[c3 * 4 + r];
            z1 = zfp[(c3 + 256) * 4 + r];
            z2 = zfp[(c3 + 512) * 4 + r];
            hp0 = (z0 - mean) * rstd * gc[c3]       + ge[c3];
            hp1 = (z1 - mean) * rstd * gc[c3 + 256] + ge[c3 + 256];
            hp2 = (z2 - mean) * rstd * gc[c3 + 512] + ge[c3 + 512];
            rg = fsig(xn0 + hp0 + gb[c3]);
            zg = fsig(xn1 + hp1 + gb[c3 + 256]);
            hh = ftanh(xn2 + rg * hp2 + gb[c3 + 512]);
            hn = zg * hprev1 + (1.0f - zg) * hh;
            float ho1 = mt ? hn : hprev1;
            hprev1 = ho1;
            hsf[r * 256 + c3] = ho1;

            if (rank == 0) {
                long gbase = (long)(t * Bn + myrow) * Hn;
                g_hseq[gbase + c2] = ho0;
                g_hseq[gbase + c3] = ho1;
            }
        }
        __syncthreads();   // hsf(t) ready for next GEMV (local only)
    }
    cluster_sync();
}

// ---------------------------------------------------------------------------
// Action pass (per depth, after scan): logits/policy/action + next mask.
// a = tanh(xa_raw + axz + ba1); l = a @ Wa2 + ba2.  Block = 2 rows x 128 thr.
// ---------------------------------------------------------------------------
__global__ void __launch_bounds__(256) act2_k(
    const float* __restrict__ ba1, const float* __restrict__ wa2,
    const float* __restrict__ ba2,
    float* __restrict__ out, int out_size, int dep)
{
    __shared__ float red[2][4][2];
    const int rr = threadIdx.x >> 7;
    const int j  = threadIdx.x & 127;
    const long row = (long)blockIdx.x * 2 + rr;

    float a = tanhf(g_xpz[row * XPW + H3 + j] + g_axz[row * An + j] + ba1[j]);
    float p0 = a * wa2[2 * j];
    float p1 = a * wa2[2 * j + 1];
#pragma unroll
    for (int o = 16; o; o >>= 1) {
        p0 += __shfl_xor_sync(0xffffffffu, p0, o);
        p1 += __shfl_xor_sync(0xffffffffu, p1, o);
    }
    int w = (threadIdx.x >> 5) & 3;
    if ((threadIdx.x & 31) == 0) { red[rr][w][0] = p0; red[rr][w][1] = p1; }
    __syncthreads();
    if (j == 0) {
        float l0 = ba2[0], l1 = ba2[1];
#pragma unroll
        for (int q = 0; q < 4; q++) { l0 += red[rr][q][0]; l1 += red[rr][q][1]; }
        int t = (int)(row >> 6), b = (int)(row & 63);
        int m = g_maskD[dep][row];
        int act = (l1 > l0) && m;      // pol1>pol0 <=> l1>l0 (softmax monotone)
        float mx = fmaxf(l0, l1);
        float e0 = expf(l0 - mx), e1 = expf(l1 - mx);
        float inv = 1.0f / (e0 + e1);
        int ai = OUT_ACT + (b * NDEPTH + dep) * Ln + t;
        if (ai < out_size) out[ai] = (float)act;
        int pi = OUT_POL + ((b * NDEPTH + dep) * Ln + t) * 2;
        if (pi + 1 < out_size) { out[pi] = e0 * inv; out[pi + 1] = e1 * inv; }
        g_maskD[dep + 1][row] = (unsigned char)act;
    }
}

// ---------------------------------------------------------------------------
// output = h_seq[-1] (t = 511), (B, H)
// ---------------------------------------------------------------------------
__global__ void copyout_k(float* __restrict__ out, int out_size)
{
    int i = blockIdx.x * blockDim.x + threadIdx.x;
    if (i < Bn * Hn && i < out_size)
        out[i] = g_hseq[(long)(511 * Bn + (i >> 8)) * Hn + (i & 255)];
}

// ---------------------------------------------------------------------------
// launch
// ---------------------------------------------------------------------------
extern "C" void kernel_launch(void* const* d_in, const int* in_sizes, int n_in,
                              void* d_out, int out_size)
{
    const float* x      = (const float*)d_in[0];
    const int*   maskp  = (const int*)  d_in[1];
    const float* W_emb  = (const float*)d_in[2];
    const float* b_emb  = (const float*)d_in[3];
    const float* W      = (const float*)d_in[4];
    const float* U      = (const float*)d_in[5];
    const float* b      = (const float*)d_in[6];
    const float* Wa1    = (const float*)d_in[7];
    const float* Ua1    = (const float*)d_in[8];
    const float* ba1    = (const float*)d_in[9];
    const float* Wa2    = (const float*)d_in[10];
    const float* ba2    = (const float*)d_in[11];
    const float* gammas = (const float*)d_in[12];
    const float* betas  = (const float*)d_in[13];
    float* out = (float*)d_out;

    static int attr_done = 0;
    if (!attr_done) {
        cudaFuncSetAttribute(scan_k, cudaFuncAttributeMaxDynamicSharedMemorySize,
                             SCAN_SMEM);
        attr_done = 1;
    }

    // 1: prep (pack W/Wa1, transpose U, init mask)
    prep_k<<<(PREP_TOT + 255) / 256, 256>>>(W, Wa1, U, maskp);
    // 2: embedding  g_hseq = permute(x) @ W_emb + b_emb
    gemm_k<<<dim3(2, 256), 256>>>(x, W_emb, b_emb, 256, 0);

    for (int d = 0; d < NDEPTH; d++) {
        // 3: projection g_xpz = g_hseq @ [W | Wa1]  (raw; LN fused in scan)
        gemm_k<<<dim3(7, 256), 256>>>(nullptr, nullptr, nullptr, XPW, 1);
        // 4: recurrence (fused xp LN + GRU gates)  <- ncu-captured slot
        scan_k<<<128, 512, SCAN_SMEM>>>(b, gammas, betas,
                                        gammas + H3, betas + H3, d);
        // 5: action pass
        gemm_k<<<dim3(1, 256), 256>>>(nullptr, Ua1, nullptr, An, 2);
        act2_k<<<NROWS / 2, 256>>>(ba1, Wa2, ba2, out, out_size, d);
    }

    copyout_k<<<64, 256>>>(out, out_size);
}